// round 13
// baseline (speedup 1.0000x reference)
#include <cuda_runtime.h>
#include <math.h>

#define Bq 4096
#define Sq 512
#define NT 512
#define NB 128
#define RPB 32
#define KST 76                 // row: h[0:64) | x[64:75) | pad(75)
#define GROWS 8
#define HBG (GROWS*KST)        // 608 floats per group buffer

typedef unsigned long long ull;

// shared layout (float offsets)
#define O_WP   0                       // wp [38 kk][32 c2][20] = 24320
#define O_HB   24320                   // [4 grp][2 buf][608]   = 4864
#define O_WOUT (O_HB + 4*2*HBG)        // 128
#define O_SC   (O_WOUT + 128)          // 32
#define O_ISC  (O_SC + 32)             // 32
#define SM_TOTAL (O_ISC + 32)
#define SMEM_BYTES (SM_TOTAL*4)        // ~117.5 KB

__device__ __forceinline__ float sigf(float x){ return 1.0f/(1.0f+__expf(-x)); }
__device__ __forceinline__ float tanh_f(float x){ return 2.0f/(1.0f+__expf(-2.0f*x)) - 1.0f; }

__device__ __forceinline__ void ffma2(ull &d, ull a, ull b){
    asm("fma.rn.f32x2 %0, %1, %2, %0;" : "+l"(d) : "l"(a), "l"(b));
}
__device__ __forceinline__ float fold2(ull v){
    float2 f; asm("mov.b64 {%0,%1}, %2;" : "=f"(f.x), "=f"(f.y) : "l"(v));
    return f.x + f.y;
}
__device__ __forceinline__ void gbar(int id){
    asm volatile("bar.sync %0, 128;" :: "r"(id) : "memory");
}

__global__ void __launch_bounds__(NT,1)
deepar_kernel(const float* __restrict__ target,
              const float* __restrict__ covar,
              const int*   __restrict__ cats,
              const float* __restrict__ scale,
              const float* __restrict__ e0,
              const float* __restrict__ e1,
              const float* __restrict__ e2,
              const float* __restrict__ e3,
              const float* __restrict__ w_ih,
              const float* __restrict__ w_hh,
              const float* __restrict__ bias,
              const float* __restrict__ w_out,
              const float* __restrict__ b_out,
              float* __restrict__ out)
{
    extern __shared__ float sm[];
    float* wp_s   = sm + O_WP;
    float* hball  = sm + O_HB;
    float* wout_s = sm + O_WOUT;
    float* sc_s   = sm + O_SC;
    float* isc_s  = sm + O_ISC;
    float* sx_s   = sm + O_WP;     // alias: static_x [32][66], prologue only

    const int tid  = threadIdx.x;
    const int row0 = blockIdx.x * RPB;

    // ---- stage static_x [32][66] ----
    for (int e = tid; e < RPB*65; e += NT){
        int r = e / 65, j = e - r*65;
        int b = row0 + r;
        float v;
        if (j < 64){
            int tsel = j >> 4, jj = j & 15;
            int c = cats[b*4 + tsel];
            const float* et = (tsel==0)?e0:(tsel==1)?e1:(tsel==2)?e2:e3;
            v = et[c*16 + jj];
        } else {
            v = log1pf(scale[b]);
        }
        sx_s[r*66 + j] = v;
    }
    __syncthreads();

    // ---- mapping: group(128 thr) owns 8 rows x 64 cells; warp = 16 cells ----
    const int grp   = tid >> 7;            // 0..3
    const int gLane = tid & 127;
    const int wg    = (tid >> 5) & 3;      // warp in group
    const int lane  = tid & 31;
    const int gl    = lane & 7;            // cell-pair group in warp
    const int rl    = lane >> 3;           // row-pair group (0..3)
    const int cbase = wg*16 + gl*2;        // cells cbase, cbase+1
    const int c2i   = cbase >> 1;          // 0..31
    const int r0l   = 2*rl;                // local rows r0l, r0l+1
    float* hb_g = hball + grp*2*HBG;

    // ---- pre[rr][cc][t] = bias + static_x @ w_ih[11:76] (registers) ----
    float pre[2][2][4];
    {
        #pragma unroll
        for (int cc = 0; cc < 2; cc++)
            #pragma unroll
            for (int t = 0; t < 4; t++){
                float bv = bias[t*64 + cbase + cc];
                pre[0][cc][t] = bv; pre[1][cc][t] = bv;
            }
        for (int k = 0; k < 65; k++){
            float2 wv[4];
            #pragma unroll
            for (int t = 0; t < 4; t++)
                wv[t] = *(const float2*)(w_ih + (11+k)*256 + t*64 + cbase);
            float xv0 = sx_s[(grp*GROWS + r0l    )*66 + k];
            float xv1 = sx_s[(grp*GROWS + r0l + 1)*66 + k];
            #pragma unroll
            for (int t = 0; t < 4; t++){
                pre[0][0][t] = fmaf(xv0, wv[t].x, pre[0][0][t]);
                pre[0][1][t] = fmaf(xv0, wv[t].y, pre[0][1][t]);
                pre[1][0][t] = fmaf(xv1, wv[t].x, pre[1][0][t]);
                pre[1][1][t] = fmaf(xv1, wv[t].y, pre[1][1][t]);
            }
        }
    }
    __syncthreads();   // sx reads done; wp_s reusable

    // ---- pack weights: wp[kk][c2][20]: +tp*8+clo*4 = {w2k,Ta; w2k1,Ta; w2k,Tb; w2k1,Tb}
    #define WK(k,g) ((k) < 64 ? w_hh[(k)*256 + (g)] : ((k) < 75 ? w_ih[((k)-64)*256 + (g)] : 0.0f))
    for (int s = tid; s < 38*64*2; s += NT){
        int tp = s & 1;
        int c  = (s >> 1) & 63;
        int kk = s >> 7;
        int c2 = c >> 1, clo = c & 1;
        float* dst = wp_s + (kk*32 + c2)*20 + tp*8 + clo*4;
        int k0 = 2*kk, k1 = 2*kk + 1;
        int ga = (tp*2    )*64 + c;
        int gb = (tp*2 + 1)*64 + c;
        dst[0] = WK(k0, ga);
        dst[1] = WK(k1, ga);
        dst[2] = WK(k0, gb);
        dst[3] = WK(k1, gb);
    }
    #undef WK
    if (tid < 128) wout_s[tid] = w_out[tid];
    if (tid < RPB){
        float s = scale[row0 + tid];
        sc_s[tid]  = s;
        isc_s[tid] = 1.0f / fmaxf(s, 1e-4f);
    }
    for (int i = tid; i < 4*2*HBG; i += NT) hball[i] = 0.0f;
    __syncthreads();

    // ---- x ownership: gLane 0..95 -> (8 rows x 12 j) per group ----
    int xrow = 0, xj = 0, xb = 0;
    const bool xown = (gLane < 96);
    float xreg = 0.0f;
    if (xown){
        xrow = gLane / 12;               // local row 0..7
        xj   = gLane % 12;
        xb   = row0 + grp*GROWS + xrow;
        float v = 0.0f;
        if (xj >= 1 && xj <= 10) v = covar[(xb*Sq + 0)*10 + (xj-1)];
        hb_g[1*HBG + xrow*KST + 64 + xj] = v;   // x(0) into buf1
    }
    // head: gLane 96..111 -> (8 rows x 2)
    const bool hown = (gLane >= 96) && (gLane < 112);
    const int  hrl  = (gLane - 96) >> 1;        // local row
    const int  hws  = gLane & 1;
    const int  hr32 = grp*GROWS + hrl;          // 0..31 (for sc_s)
    __syncthreads();

    const int barid = grp + 1;
    float creg[2][2] = {{0,0},{0,0}};

    for (int t = 0; t < Sq; t++){
        gbar(barid);   // group-local: h(t-1)/x(t) visible
        const float* hb = hb_g + ((t+1)&1)*HBG;

        // head for step t-1 (stable buffer)
        if (hown && t > 0){
            const float* hr = hb + hrl*KST;
            float a0=0.f,a1=0.f,a2=0.f,a3=0.f;
            #pragma unroll 8
            for (int k = 0; k < 64; k += 4){
                a0 = fmaf(hr[k],   wout_s[2*k     + hws], a0);
                a1 = fmaf(hr[k+1], wout_s[2*(k+1) + hws], a1);
                a2 = fmaf(hr[k+2], wout_s[2*(k+2) + hws], a2);
                a3 = fmaf(hr[k+3], wout_s[2*(k+3) + hws], a3);
            }
            float a = (a0+a1)+(a2+a3) + b_out[hws];
            float sp = (a > 15.0f) ? a : log1pf(__expf(a));
            sp += 1e-4f;
            int b = row0 + grp*GROWS + hrl;
            if (hws == 0) out[b*Sq + (t-1)] = sp * sc_s[hr32];
            else          out[Bq*Sq + b*Sq + (t-1)] = sp;
        }
        // prefetch x(t+1)
        if (xown && t+1 < Sq){
            if (xj == 0)       xreg = target[xb*Sq + t] * isc_s[grp*GROWS + xrow];
            else if (xj <= 10) xreg = covar[(xb*Sq + t+1)*10 + (xj-1)];
            else               xreg = 0.0f;
        }

        // ===== GEMM: 2 rows x 2 cells x 4 types, full K (19 quads) =====
        ull acc[2][2][4];
        #pragma unroll
        for (int rr = 0; rr < 2; rr++)
            #pragma unroll
            for (int cc = 0; cc < 2; cc++)
                #pragma unroll
                for (int tp = 0; tp < 4; tp++) acc[rr][cc][tp] = 0ull;

        const float* hr0 = hb + r0l*KST;
        const float* hr1 = hb + (r0l+1)*KST;
        #pragma unroll 4
        for (int q = 0; q < 19; q++){
            ulonglong2 hA = *(const ulonglong2*)(hr0 + q*4);
            ulonglong2 hB = *(const ulonglong2*)(hr1 + q*4);
            #pragma unroll
            for (int e = 0; e < 2; e++){
                int kk = 2*q + e;
                const float* wb = wp_s + (kk*32 + c2i)*20;
                ulonglong2 u_if0 = *(const ulonglong2*)(wb + 0);   // c0: {i,f}
                ulonglong2 u_if1 = *(const ulonglong2*)(wb + 4);   // c1: {i,f}
                ulonglong2 u_go0 = *(const ulonglong2*)(wb + 8);   // c0: {g,o}
                ulonglong2 u_go1 = *(const ulonglong2*)(wb + 12);  // c1: {g,o}
                ull ha = e ? hA.y : hA.x;
                ull hbv = e ? hB.y : hB.x;
                ffma2(acc[0][0][0], ha, u_if0.x);
                ffma2(acc[0][0][1], ha, u_if0.y);
                ffma2(acc[0][0][2], ha, u_go0.x);
                ffma2(acc[0][0][3], ha, u_go0.y);
                ffma2(acc[0][1][0], ha, u_if1.x);
                ffma2(acc[0][1][1], ha, u_if1.y);
                ffma2(acc[0][1][2], ha, u_go1.x);
                ffma2(acc[0][1][3], ha, u_go1.y);
                ffma2(acc[1][0][0], hbv, u_if0.x);
                ffma2(acc[1][0][1], hbv, u_if0.y);
                ffma2(acc[1][0][2], hbv, u_go0.x);
                ffma2(acc[1][0][3], hbv, u_go0.y);
                ffma2(acc[1][1][0], hbv, u_if1.x);
                ffma2(acc[1][1][1], hbv, u_if1.y);
                ffma2(acc[1][1][2], hbv, u_go1.x);
                ffma2(acc[1][1][3], hbv, u_go1.y);
            }
        }

        // ===== fused cell: 2 rows x 2 cells, c in regs, h store =====
        {
            float* hw = hb_g + (t&1)*HBG;
            #pragma unroll
            for (int rr = 0; rr < 2; rr++){
                float2 hv;
                #pragma unroll
                for (int cc = 0; cc < 2; cc++){
                    float gi = fold2(acc[rr][cc][0]) + pre[rr][cc][0];
                    float gf = fold2(acc[rr][cc][1]) + pre[rr][cc][1];
                    float gg = fold2(acc[rr][cc][2]) + pre[rr][cc][2];
                    float go = fold2(acc[rr][cc][3]) + pre[rr][cc][3];
                    float i = sigf(gi);
                    float f = sigf(gf);
                    float g = tanh_f(gg);
                    float o = sigf(go);
                    float c = fmaf(f, creg[rr][cc], i*g);
                    creg[rr][cc] = c;
                    float h = o * tanh_f(c);
                    if (cc == 0) hv.x = h; else hv.y = h;
                }
                *(float2*)(hw + (r0l+rr)*KST + cbase) = hv;
            }
            if (xown) hw[xrow*KST + 64 + xj] = xreg;   // x(t+1)
        }
    }

    // final head for t = Sq-1
    gbar(barid);
    if (hown){
        const float* hr = hb_g + ((Sq-1)&1)*HBG + hrl*KST;
        float a0=0.f,a1=0.f,a2=0.f,a3=0.f;
        #pragma unroll 8
        for (int k = 0; k < 64; k += 4){
            a0 = fmaf(hr[k],   wout_s[2*k     + hws], a0);
            a1 = fmaf(hr[k+1], wout_s[2*(k+1) + hws], a1);
            a2 = fmaf(hr[k+2], wout_s[2*(k+2) + hws], a2);
            a3 = fmaf(hr[k+3], wout_s[2*(k+3) + hws], a3);
        }
        float a = (a0+a1)+(a2+a3) + b_out[hws];
        float sp = (a > 15.0f) ? a : log1pf(__expf(a));
        sp += 1e-4f;
        int b = row0 + grp*GROWS + hrl;
        if (hws == 0) out[b*Sq + (Sq-1)] = sp * sc_s[hr32];
        else          out[Bq*Sq + b*Sq + (Sq-1)] = sp;
    }
}

extern "C" void kernel_launch(void* const* d_in, const int* in_sizes, int n_in,
                              void* d_out, int out_size)
{
    (void)in_sizes; (void)n_in; (void)out_size;
    cudaFuncSetAttribute(deepar_kernel,
                         cudaFuncAttributeMaxDynamicSharedMemorySize, SMEM_BYTES);
    deepar_kernel<<<NB, NT, SMEM_BYTES>>>(
        (const float*)d_in[0],   // target
        (const float*)d_in[1],   // covariates
        (const int*)  d_in[2],   // static_cats
        (const float*)d_in[3],   // scale
        (const float*)d_in[4],   // emb0
        (const float*)d_in[5],   // emb1
        (const float*)d_in[6],   // emb2
        (const float*)d_in[7],   // emb3
        (const float*)d_in[8],   // w_ih
        (const float*)d_in[9],   // w_hh
        (const float*)d_in[10],  // bias
        (const float*)d_in[11],  // w_out
        (const float*)d_in[12],  // b_out
        (float*)d_out);
}

// round 14
// speedup vs baseline: 1.6802x; 1.6802x over previous
#include <cuda_runtime.h>
#include <math.h>

#define Bq 4096
#define Sq 512
#define NT 512
#define NB 128
#define RPB 32
#define KST 76               // unified k stride: h[0:64) | x[64:75) | pad
#define HBUFSZ (RPB*KST)     // 2432 floats per h|x buffer

typedef unsigned long long ull;

// shared layout (float offsets)
#define O_WA   0                         // wa [38 kk][64 g~] float4 = 9728
#define O_WB   (O_WA + 38*64*4)          // wb same                  = 9728
#define O_HB   (O_WB + 38*64*4)          // 2 * [32][KST]            = 4864
#define O_WOUT (O_HB + 2*HBUFSZ)         // 128
#define O_SC   (O_WOUT + 128)
#define O_ISC  (O_SC + 32)
#define SM_TOTAL (O_ISC + 32)
#define SMEM_BYTES (SM_TOTAL*4)          // ~98 KB

__device__ __forceinline__ float sigf(float x){
    float e = __expf(-x);
    return __fdividef(1.0f, 1.0f + e);
}
__device__ __forceinline__ float tanh_f(float x){
    float e = __expf(-2.0f*x);
    return __fdividef(2.0f, 1.0f + e) - 1.0f;
}

__device__ __forceinline__ void ffma2(ull &d, ull a, ull b){
    asm("fma.rn.f32x2 %0, %1, %2, %0;" : "+l"(d) : "l"(a), "l"(b));
}
__device__ __forceinline__ float fold2(ull v){
    float2 f; asm("mov.b64 {%0,%1}, %2;" : "=f"(f.x), "=f"(f.y) : "l"(v));
    return f.x + f.y;
}
__device__ __forceinline__ ull pack2(float lo, float hi){
    ull v; asm("mov.b64 %0, {%1,%2};" : "=l"(v) : "f"(lo), "f"(hi));
    return v;
}
__device__ __forceinline__ void pbar(int id){
    asm volatile("bar.sync %0, 64;" :: "r"(id) : "memory");
}

__global__ void __launch_bounds__(NT,1)
deepar_kernel(const float* __restrict__ target,
              const float* __restrict__ covar,
              const int*   __restrict__ cats,
              const float* __restrict__ scale,
              const float* __restrict__ e0,
              const float* __restrict__ e1,
              const float* __restrict__ e2,
              const float* __restrict__ e3,
              const float* __restrict__ w_ih,
              const float* __restrict__ w_hh,
              const float* __restrict__ bias,
              const float* __restrict__ w_out,
              const float* __restrict__ b_out,
              float* __restrict__ out)
{
    extern __shared__ float sm[];
    float* wa_s   = sm + O_WA;
    float* wb_s   = sm + O_WB;
    float* hbuf   = sm + O_HB;
    float* wout_s = sm + O_WOUT;
    float* sc_s   = sm + O_SC;
    float* isc_s  = sm + O_ISC;
    float* sx_s   = sm + O_WA;     // alias: static_x [32][66], pre-phase only

    const int tid  = threadIdx.x;
    const int row0 = blockIdx.x * RPB;

    // ---- phase 0: stage static_x into sx_s ----
    for (int e = tid; e < RPB*65; e += NT){
        int r = e / 65, j = e - r*65;
        int b = row0 + r;
        float v;
        if (j < 64){
            int tsel = j >> 4, jj = j & 15;
            int c = cats[b*4 + tsel];
            const float* et = (tsel==0)?e0:(tsel==1)?e1:(tsel==2)?e2:e3;
            v = et[c*16 + jj];
        } else {
            v = log1pf(scale[b]);
        }
        sx_s[r*66 + j] = v;
    }
    __syncthreads();

    // ---- thread mapping: g~ = tid&63, pair p = tid>>6 owns rows 4p..4p+3 ----
    const int gt    = tid & 63;
    const int pid   = tid >> 6;        // 0..7
    const int rbase = pid * 4;
    const int wInPair = (tid >> 5) & 1;
    const int lane  = tid & 31;
    const int pairLane = wInPair*32 + lane;   // 0..63 within pair

    // ---- pre[j][tp] = bias + static_x @ w_ih[11:76], in registers ----
    float pre[4][4];
    {
        #pragma unroll
        for (int tp = 0; tp < 4; tp++){
            float bv = bias[tp*64 + gt];
            #pragma unroll
            for (int j = 0; j < 4; j++) pre[j][tp] = bv;
        }
        for (int k = 0; k < 65; k++){
            const float* wr = w_ih + (11+k)*256 + gt;
            float w0 = wr[0], w1 = wr[64], w2 = wr[128], w3 = wr[192];
            #pragma unroll
            for (int j = 0; j < 4; j++){
                float xv = sx_s[(rbase+j)*66 + k];
                pre[j][0] = fmaf(xv, w0, pre[j][0]);
                pre[j][1] = fmaf(xv, w1, pre[j][1]);
                pre[j][2] = fmaf(xv, w2, pre[j][2]);
                pre[j][3] = fmaf(xv, w3, pre[j][3]);
            }
        }
    }
    __syncthreads();   // sx readers done; wa_s can be overwritten

    // ---- pack weights: wa[kk][g~] = {i:kpair, f:kpair}, wb = {g:kpair, o:kpair} ----
    for (int idx = tid; idx < 38*64; idx += NT){
        int kk = idx >> 6, g = idx & 63;
        int k0 = 2*kk, k1 = 2*kk + 1;
        #define WK(k,c) ((k) < 64 ? w_hh[(k)*256 + (c)] : ((k) < 75 ? w_ih[((k)-64)*256 + (c)] : 0.0f))
        float4 a4, b4;
        a4.x = WK(k0, g);        a4.y = WK(k1, g);
        a4.z = WK(k0, 64 + g);   a4.w = WK(k1, 64 + g);
        b4.x = WK(k0, 128 + g);  b4.y = WK(k1, 128 + g);
        b4.z = WK(k0, 192 + g);  b4.w = WK(k1, 192 + g);
        #undef WK
        *(float4*)(wa_s + idx*4) = a4;
        *(float4*)(wb_s + idx*4) = b4;
    }
    if (tid < 128) wout_s[tid] = w_out[tid];
    if (tid < RPB){
        float s = scale[row0 + tid];
        sc_s[tid]  = s;
        isc_s[tid] = 1.0f / fmaxf(s, 1e-4f);
    }
    for (int i = tid; i < 2*HBUFSZ; i += NT) hbuf[i] = 0.0f;
    __syncthreads();

    // ---- per-pair x ownership: pairLane 0..47 cover (4 rows x 12 j) ----
    int xrow = 0, xj = 0, xb = 0;
    const bool xown = (pairLane < 48);
    float xreg = 0.0f;
    if (xown){
        xrow = rbase + (pairLane / 12);
        xj   = pairLane % 12;
        xb   = row0 + xrow;
        float v = 0.0f;
        if (xj >= 1 && xj <= 10) v = covar[(xb*Sq + 0)*10 + (xj-1)];
        hbuf[1*HBUFSZ + xrow*KST + 64 + xj] = v;   // x(0): prev=0, cov(0)
    }
    // head ownership: warp1-of-pair lanes 0..7 -> (4 rows x 2 outputs)
    const bool hown = (wInPair == 1) && (lane < 8);
    const int  hr_  = rbase + (lane >> 1);
    const int  hws  = lane & 1;
    __syncthreads();

    const int barid = pid + 1;
    float creg[4] = {0.0f, 0.0f, 0.0f, 0.0f};

    for (int t = 0; t < Sq; t++){
        pbar(barid);   // pair-local: h(t-1)/x(t) of rows rbase..rbase+3 are visible
        const float* hb = hbuf + ((t+1)&1)*HBUFSZ;   // h(t-1) | x(t)

        // head for step t-1 (reads stable hb rows of this pair)
        if (hown && t > 0){
            const float* hr = hb + hr_*KST;
            float a0=0.f,a1=0.f,a2=0.f,a3=0.f;
            #pragma unroll 8
            for (int k = 0; k < 64; k += 4){
                a0 = fmaf(hr[k],   wout_s[2*k     + hws], a0);
                a1 = fmaf(hr[k+1], wout_s[2*(k+1) + hws], a1);
                a2 = fmaf(hr[k+2], wout_s[2*(k+2) + hws], a2);
                a3 = fmaf(hr[k+3], wout_s[2*(k+3) + hws], a3);
            }
            float a = (a0+a1)+(a2+a3) + b_out[hws];
            float sp = (a > 15.0f) ? a : log1pf(__expf(a));
            sp += 1e-4f;
            int b = row0 + hr_;
            if (hws == 0) out[b*Sq + (t-1)] = sp * sc_s[hr_];
            else          out[Bq*Sq + b*Sq + (t-1)] = sp;
        }
        // prefetch x(t+1)
        if (xown && t+1 < Sq){
            if (xj == 0)       xreg = target[xb*Sq + t] * isc_s[xrow];
            else if (xj <= 10) xreg = covar[(xb*Sq + t+1)*10 + (xj-1)];
            else               xreg = 0.0f;
        }

        // ================= GEMM: all 4 gate types for (4 rows x g~) =================
        // acc initialized with pre in the low half -> fold2 yields gate+pre
        ull acc[4][4];
        #pragma unroll
        for (int j = 0; j < 4; j++)
            #pragma unroll
            for (int tp = 0; tp < 4; tp++) acc[j][tp] = pack2(pre[j][tp], 0.0f);

        #pragma unroll
        for (int kk2 = 0; kk2 < 19; kk2++){
            ulonglong2 wa0 = *(const ulonglong2*)(wa_s + ((2*kk2  )*64 + gt)*4);
            ulonglong2 wb0 = *(const ulonglong2*)(wb_s + ((2*kk2  )*64 + gt)*4);
            ulonglong2 wa1 = *(const ulonglong2*)(wa_s + ((2*kk2+1)*64 + gt)*4);
            ulonglong2 wb1 = *(const ulonglong2*)(wb_s + ((2*kk2+1)*64 + gt)*4);
            #pragma unroll
            for (int j = 0; j < 4; j++){
                ulonglong2 hv = *(const ulonglong2*)(hb + (rbase+j)*KST + kk2*4);
                ffma2(acc[j][0], hv.x, wa0.x);
                ffma2(acc[j][1], hv.x, wa0.y);
                ffma2(acc[j][2], hv.x, wb0.x);
                ffma2(acc[j][3], hv.x, wb0.y);
                ffma2(acc[j][0], hv.y, wa1.x);
                ffma2(acc[j][1], hv.y, wa1.y);
                ffma2(acc[j][2], hv.y, wb1.x);
                ffma2(acc[j][3], hv.y, wb1.y);
            }
        }

        // ================= fused LSTM cell (registers) + h store =================
        {
            float* hw = hbuf + (t&1)*HBUFSZ;
            #pragma unroll
            for (int j = 0; j < 4; j++){
                float gi = fold2(acc[j][0]);
                float gf = fold2(acc[j][1]);
                float gg = fold2(acc[j][2]);
                float go = fold2(acc[j][3]);
                float i = sigf(gi);
                float f = sigf(gf);
                float g = tanh_f(gg);
                float o = sigf(go);
                float c = fmaf(f, creg[j], i*g);
                creg[j] = c;
                hw[(rbase+j)*KST + gt] = o * tanh_f(c);
            }
            if (xown) hw[xrow*KST + 64 + xj] = xreg;   // x(t+1)
        }
    }

    // final head for t = Sq-1 (pair-local sync, then read hbuf[(Sq-1)&1])
    pbar(barid);
    if (hown){
        const float* hr = hbuf + ((Sq-1)&1)*HBUFSZ + hr_*KST;
        float a0=0.f,a1=0.f,a2=0.f,a3=0.f;
        #pragma unroll 8
        for (int k = 0; k < 64; k += 4){
            a0 = fmaf(hr[k],   wout_s[2*k     + hws], a0);
            a1 = fmaf(hr[k+1], wout_s[2*(k+1) + hws], a1);
            a2 = fmaf(hr[k+2], wout_s[2*(k+2) + hws], a2);
            a3 = fmaf(hr[k+3], wout_s[2*(k+3) + hws], a3);
        }
        float a = (a0+a1)+(a2+a3) + b_out[hws];
        float sp = (a > 15.0f) ? a : log1pf(__expf(a));
        sp += 1e-4f;
        int b = row0 + hr_;
        if (hws == 0) out[b*Sq + (Sq-1)] = sp * sc_s[hr_];
        else          out[Bq*Sq + b*Sq + (Sq-1)] = sp;
    }
}

extern "C" void kernel_launch(void* const* d_in, const int* in_sizes, int n_in,
                              void* d_out, int out_size)
{
    (void)in_sizes; (void)n_in; (void)out_size;
    cudaFuncSetAttribute(deepar_kernel,
                         cudaFuncAttributeMaxDynamicSharedMemorySize, SMEM_BYTES);
    deepar_kernel<<<NB, NT, SMEM_BYTES>>>(
        (const float*)d_in[0],   // target
        (const float*)d_in[1],   // covariates
        (const int*)  d_in[2],   // static_cats
        (const float*)d_in[3],   // scale
        (const float*)d_in[4],   // emb0
        (const float*)d_in[5],   // emb1
        (const float*)d_in[6],   // emb2
        (const float*)d_in[7],   // emb3
        (const float*)d_in[8],   // w_ih
        (const float*)d_in[9],   // w_hh
        (const float*)d_in[10],  // bias
        (const float*)d_in[11],  // w_out
        (const float*)d_in[12],  // b_out
        (float*)d_out);
}

// round 15
// speedup vs baseline: 1.7657x; 1.0509x over previous
#include <cuda_runtime.h>
#include <math.h>

#define Bq 4096
#define Sq 512
#define NT 512
#define NB 128
#define RPB 32
#define KST 76               // unified k stride: h[0:64) | x[64:75) | pad
#define HBUFSZ (RPB*KST)     // 2432 floats per h|x buffer

typedef unsigned long long ull;

// shared layout (float offsets)
#define O_WA   0                         // wa [38 kk][64 g~] float4 = 9728
#define O_WB   (O_WA + 38*64*4)          // wb same                  = 9728
#define O_HB   (O_WB + 38*64*4)          // 2 * [32][KST]            = 4864
#define O_WOUT (O_HB + 2*HBUFSZ)         // wout TRANSPOSED [2][64]  = 128
#define O_SC   (O_WOUT + 128)
#define O_ISC  (O_SC + 32)
#define SM_TOTAL (O_ISC + 32)
#define SMEM_BYTES (SM_TOTAL*4)          // ~98 KB

__device__ __forceinline__ float sigf(float x){
    float e = __expf(-x);
    return __fdividef(1.0f, 1.0f + e);
}
__device__ __forceinline__ float tanh_f(float x){
    float e = __expf(-2.0f*x);
    return __fdividef(2.0f, 1.0f + e) - 1.0f;
}

__device__ __forceinline__ void ffma2(ull &d, ull a, ull b){
    asm("fma.rn.f32x2 %0, %1, %2, %0;" : "+l"(d) : "l"(a), "l"(b));
}
__device__ __forceinline__ float fold2(ull v){
    float2 f; asm("mov.b64 {%0,%1}, %2;" : "=f"(f.x), "=f"(f.y) : "l"(v));
    return f.x + f.y;
}
__device__ __forceinline__ ull pack2(float lo, float hi){
    ull v; asm("mov.b64 %0, {%1,%2};" : "=l"(v) : "f"(lo), "f"(hi));
    return v;
}
__device__ __forceinline__ void pbar(int id){
    asm volatile("bar.sync %0, 64;" :: "r"(id) : "memory");
}

__global__ void __launch_bounds__(NT,1)
deepar_kernel(const float* __restrict__ target,
              const float* __restrict__ covar,
              const int*   __restrict__ cats,
              const float* __restrict__ scale,
              const float* __restrict__ e0,
              const float* __restrict__ e1,
              const float* __restrict__ e2,
              const float* __restrict__ e3,
              const float* __restrict__ w_ih,
              const float* __restrict__ w_hh,
              const float* __restrict__ bias,
              const float* __restrict__ w_out,
              const float* __restrict__ b_out,
              float* __restrict__ out)
{
    extern __shared__ float sm[];
    float* wa_s   = sm + O_WA;
    float* wb_s   = sm + O_WB;
    float* hbuf   = sm + O_HB;
    float* wout_s = sm + O_WOUT;
    float* sc_s   = sm + O_SC;
    float* isc_s  = sm + O_ISC;
    float* sx_s   = sm + O_WA;     // alias: static_x [32][66], pre-phase only

    const int tid  = threadIdx.x;
    const int row0 = blockIdx.x * RPB;

    // ---- phase 0: stage static_x into sx_s ----
    for (int e = tid; e < RPB*65; e += NT){
        int r = e / 65, j = e - r*65;
        int b = row0 + r;
        float v;
        if (j < 64){
            int tsel = j >> 4, jj = j & 15;
            int c = cats[b*4 + tsel];
            const float* et = (tsel==0)?e0:(tsel==1)?e1:(tsel==2)?e2:e3;
            v = et[c*16 + jj];
        } else {
            v = log1pf(scale[b]);
        }
        sx_s[r*66 + j] = v;
    }
    __syncthreads();

    // ---- thread mapping: g~ = tid&63, pair p = tid>>6 owns rows 4p..4p+3 ----
    const int gt    = tid & 63;
    const int pid   = tid >> 6;        // 0..7
    const int rbase = pid * 4;
    const int wInPair = (tid >> 5) & 1;
    const int lane  = tid & 31;
    const int pairLane = wInPair*32 + lane;   // 0..63 within pair

    // ---- pre[j][tp] = bias + static_x @ w_ih[11:76], in registers ----
    float pre[4][4];
    {
        #pragma unroll
        for (int tp = 0; tp < 4; tp++){
            float bv = bias[tp*64 + gt];
            #pragma unroll
            for (int j = 0; j < 4; j++) pre[j][tp] = bv;
        }
        for (int k = 0; k < 65; k++){
            const float* wr = w_ih + (11+k)*256 + gt;
            float w0 = wr[0], w1 = wr[64], w2 = wr[128], w3 = wr[192];
            #pragma unroll
            for (int j = 0; j < 4; j++){
                float xv = sx_s[(rbase+j)*66 + k];
                pre[j][0] = fmaf(xv, w0, pre[j][0]);
                pre[j][1] = fmaf(xv, w1, pre[j][1]);
                pre[j][2] = fmaf(xv, w2, pre[j][2]);
                pre[j][3] = fmaf(xv, w3, pre[j][3]);
            }
        }
    }
    __syncthreads();   // sx readers done; wa_s can be overwritten

    // ---- pack weights: wa[kk][g~] = {i:kpair, f:kpair}, wb = {g:kpair, o:kpair} ----
    for (int idx = tid; idx < 38*64; idx += NT){
        int kk = idx >> 6, g = idx & 63;
        int k0 = 2*kk, k1 = 2*kk + 1;
        #define WK(k,c) ((k) < 64 ? w_hh[(k)*256 + (c)] : ((k) < 75 ? w_ih[((k)-64)*256 + (c)] : 0.0f))
        float4 a4, b4;
        a4.x = WK(k0, g);        a4.y = WK(k1, g);
        a4.z = WK(k0, 64 + g);   a4.w = WK(k1, 64 + g);
        b4.x = WK(k0, 128 + g);  b4.y = WK(k1, 128 + g);
        b4.z = WK(k0, 192 + g);  b4.w = WK(k1, 192 + g);
        #undef WK
        *(float4*)(wa_s + idx*4) = a4;
        *(float4*)(wb_s + idx*4) = b4;
    }
    // wout transposed: wout_s[col*64 + k] = w_out[k*2 + col]
    if (tid < 128) wout_s[(tid & 1)*64 + (tid >> 1)] = w_out[tid];
    if (tid < RPB){
        float s = scale[row0 + tid];
        sc_s[tid]  = s;
        isc_s[tid] = 1.0f / fmaxf(s, 1e-4f);
    }
    for (int i = tid; i < 2*HBUFSZ; i += NT) hbuf[i] = 0.0f;
    __syncthreads();

    // ---- per-pair x ownership: pairLane 0..47 cover (4 rows x 12 j) ----
    int xrow = 0, xj = 0, xb = 0;
    const bool xown = (pairLane < 48);
    float xreg = 0.0f;
    if (xown){
        xrow = rbase + (pairLane / 12);
        xj   = pairLane % 12;
        xb   = row0 + xrow;
        float v = 0.0f;
        if (xj >= 1 && xj <= 10) v = covar[(xb*Sq + 0)*10 + (xj-1)];
        hbuf[1*HBUFSZ + xrow*KST + 64 + xj] = v;   // x(0): prev=0, cov(0)
    }
    // head ownership: warp1-of-pair lanes 0..7 -> (4 rows x 2 outputs)
    const bool hown = (wInPair == 1) && (lane < 8);
    const int  hr_  = rbase + (lane >> 1);
    const int  hws  = lane & 1;
    __syncthreads();

    const int barid = pid + 1;
    float creg[4] = {0.0f, 0.0f, 0.0f, 0.0f};

    for (int t = 0; t < Sq; t++){
        pbar(barid);   // pair-local: h(t-1)/x(t) of rows rbase..rbase+3 are visible
        const float* hb = hbuf + ((t+1)&1)*HBUFSZ;   // h(t-1) | x(t)

        // head for step t-1 (vectorized: float4 over h row and transposed wout)
        if (hown && t > 0){
            const float4* hr4 = (const float4*)(hb + hr_*KST);
            const float4* wo4 = (const float4*)(wout_s + hws*64);
            float a0=0.f,a1=0.f,a2=0.f,a3=0.f;
            #pragma unroll
            for (int kq = 0; kq < 16; kq++){
                float4 hv = hr4[kq];
                float4 wv = wo4[kq];
                a0 = fmaf(hv.x, wv.x, a0);
                a1 = fmaf(hv.y, wv.y, a1);
                a2 = fmaf(hv.z, wv.z, a2);
                a3 = fmaf(hv.w, wv.w, a3);
            }
            float a = (a0+a1)+(a2+a3) + b_out[hws];
            float sp = (a > 15.0f) ? a : log1pf(__expf(a));
            sp += 1e-4f;
            int b = row0 + hr_;
            if (hws == 0) out[b*Sq + (t-1)] = sp * sc_s[hr_];
            else          out[Bq*Sq + b*Sq + (t-1)] = sp;
        }
        // prefetch x(t+1)
        if (xown && t+1 < Sq){
            if (xj == 0)       xreg = target[xb*Sq + t] * isc_s[xrow];
            else if (xj <= 10) xreg = covar[(xb*Sq + t+1)*10 + (xj-1)];
            else               xreg = 0.0f;
        }

        // ================= GEMM: all 4 gate types for (4 rows x g~) =================
        // acc initialized with pre in the low half -> fold2 yields gate+pre
        ull acc[4][4];
        #pragma unroll
        for (int j = 0; j < 4; j++)
            #pragma unroll
            for (int tp = 0; tp < 4; tp++) acc[j][tp] = pack2(pre[j][tp], 0.0f);

        #pragma unroll
        for (int kk2 = 0; kk2 < 19; kk2++){
            ulonglong2 wa0 = *(const ulonglong2*)(wa_s + ((2*kk2  )*64 + gt)*4);
            ulonglong2 wb0 = *(const ulonglong2*)(wb_s + ((2*kk2  )*64 + gt)*4);
            ulonglong2 wa1 = *(const ulonglong2*)(wa_s + ((2*kk2+1)*64 + gt)*4);
            ulonglong2 wb1 = *(const ulonglong2*)(wb_s + ((2*kk2+1)*64 + gt)*4);
            #pragma unroll
            for (int j = 0; j < 4; j++){
                ulonglong2 hv = *(const ulonglong2*)(hb + (rbase+j)*KST + kk2*4);
                ffma2(acc[j][0], hv.x, wa0.x);
                ffma2(acc[j][1], hv.x, wa0.y);
                ffma2(acc[j][2], hv.x, wb0.x);
                ffma2(acc[j][3], hv.x, wb0.y);
                ffma2(acc[j][0], hv.y, wa1.x);
                ffma2(acc[j][1], hv.y, wa1.y);
                ffma2(acc[j][2], hv.y, wb1.x);
                ffma2(acc[j][3], hv.y, wb1.y);
            }
        }

        // ================= fused LSTM cell (registers) + h store =================
        {
            float* hw = hbuf + (t&1)*HBUFSZ;
            #pragma unroll
            for (int j = 0; j < 4; j++){
                float gi = fold2(acc[j][0]);
                float gf = fold2(acc[j][1]);
                float gg = fold2(acc[j][2]);
                float go = fold2(acc[j][3]);
                float i = sigf(gi);
                float f = sigf(gf);
                float g = tanh_f(gg);
                float o = sigf(go);
                float c = fmaf(f, creg[j], i*g);
                creg[j] = c;
                hw[(rbase+j)*KST + gt] = o * tanh_f(c);
            }
            if (xown) hw[xrow*KST + 64 + xj] = xreg;   // x(t+1)
        }
    }

    // final head for t = Sq-1 (pair-local sync, then read hbuf[(Sq-1)&1])
    pbar(barid);
    if (hown){
        const float4* hr4 = (const float4*)(hbuf + ((Sq-1)&1)*HBUFSZ + hr_*KST);
        const float4* wo4 = (const float4*)(wout_s + hws*64);
        float a0=0.f,a1=0.f,a2=0.f,a3=0.f;
        #pragma unroll
        for (int kq = 0; kq < 16; kq++){
            float4 hv = hr4[kq];
            float4 wv = wo4[kq];
            a0 = fmaf(hv.x, wv.x, a0);
            a1 = fmaf(hv.y, wv.y, a1);
            a2 = fmaf(hv.z, wv.z, a2);
            a3 = fmaf(hv.w, wv.w, a3);
        }
        float a = (a0+a1)+(a2+a3) + b_out[hws];
        float sp = (a > 15.0f) ? a : log1pf(__expf(a));
        sp += 1e-4f;
        int b = row0 + hr_;
        if (hws == 0) out[b*Sq + (Sq-1)] = sp * sc_s[hr_];
        else          out[Bq*Sq + b*Sq + (Sq-1)] = sp;
    }
}

extern "C" void kernel_launch(void* const* d_in, const int* in_sizes, int n_in,
                              void* d_out, int out_size)
{
    (void)in_sizes; (void)n_in; (void)out_size;
    cudaFuncSetAttribute(deepar_kernel,
                         cudaFuncAttributeMaxDynamicSharedMemorySize, SMEM_BYTES);
    deepar_kernel<<<NB, NT, SMEM_BYTES>>>(
        (const float*)d_in[0],   // target
        (const float*)d_in[1],   // covariates
        (const int*)  d_in[2],   // static_cats
        (const float*)d_in[3],   // scale
        (const float*)d_in[4],   // emb0
        (const float*)d_in[5],   // emb1
        (const float*)d_in[6],   // emb2
        (const float*)d_in[7],   // emb3
        (const float*)d_in[8],   // w_ih
        (const float*)d_in[9],   // w_hh
        (const float*)d_in[10],  // bias
        (const float*)d_in[11],  // w_out
        (const float*)d_in[12],  // b_out
        (float*)d_out);
}

// round 16
// speedup vs baseline: 1.7767x; 1.0062x over previous
#include <cuda_runtime.h>
#include <math.h>

#define Bq 4096
#define Sq 512
#define NT 448
#define NBLK 148
#define NPAIRS 1024            // 4096 rows / 4 rows-per-pair
#define PMAX 7
#define KST 76                 // unified k stride: h[0:64) | x[64:75) | pad
#define HBUFSZ (PMAX*4*KST)    // 2128 floats per h|x buffer (28 rows)

typedef unsigned long long ull;

// shared layout (float offsets)
#define O_WA   0                         // wa [38 kk][64 g~] float4 = 9728
#define O_WB   (O_WA + 38*64*4)          // wb same                  = 9728
#define O_HB   (O_WB + 38*64*4)          // 2 * [28][KST]            = 4256
#define O_WOUT (O_HB + 2*HBUFSZ)         // wout TRANSPOSED [2][64]  = 128
#define O_SC   (O_WOUT + 128)            // 32
#define O_ISC  (O_SC + 32)               // 32
#define SM_TOTAL (O_ISC + 32)
#define SMEM_BYTES (SM_TOTAL*4)          // ~96 KB

__device__ __forceinline__ float sigf(float x){
    float e = __expf(-x);
    return __fdividef(1.0f, 1.0f + e);
}
__device__ __forceinline__ float tanh_f(float x){
    float e = __expf(-2.0f*x);
    return __fdividef(2.0f, 1.0f + e) - 1.0f;
}

__device__ __forceinline__ void ffma2(ull &d, ull a, ull b){
    asm("fma.rn.f32x2 %0, %1, %2, %0;" : "+l"(d) : "l"(a), "l"(b));
}
__device__ __forceinline__ float fold2(ull v){
    float2 f; asm("mov.b64 {%0,%1}, %2;" : "=f"(f.x), "=f"(f.y) : "l"(v));
    return f.x + f.y;
}
__device__ __forceinline__ ull pack2(float lo, float hi){
    ull v; asm("mov.b64 %0, {%1,%2};" : "=l"(v) : "f"(lo), "f"(hi));
    return v;
}
__device__ __forceinline__ void pbar(int id){
    asm volatile("bar.sync %0, 64;" :: "r"(id) : "memory");
}

__global__ void __launch_bounds__(NT,1)
deepar_kernel(const float* __restrict__ target,
              const float* __restrict__ covar,
              const int*   __restrict__ cats,
              const float* __restrict__ scale,
              const float* __restrict__ e0,
              const float* __restrict__ e1,
              const float* __restrict__ e2,
              const float* __restrict__ e3,
              const float* __restrict__ w_ih,
              const float* __restrict__ w_hh,
              const float* __restrict__ bias,
              const float* __restrict__ w_out,
              const float* __restrict__ b_out,
              float* __restrict__ out)
{
    extern __shared__ float sm[];
    float* wa_s   = sm + O_WA;
    float* wb_s   = sm + O_WB;
    float* hbuf   = sm + O_HB;
    float* wout_s = sm + O_WOUT;
    float* sc_s   = sm + O_SC;
    float* isc_s  = sm + O_ISC;
    float* sx_s   = sm + O_WA;     // alias: static_x [28][66], pre-phase only

    const int tid  = threadIdx.x;
    // balanced pair partition over blocks
    const int ps     = (int)(((long long)blockIdx.x * NPAIRS) / NBLK);
    const int pe     = (int)(((long long)(blockIdx.x+1) * NPAIRS) / NBLK);
    const int npair  = pe - ps;          // 6 or 7
    const int nrows  = npair * 4;
    const int grow0  = ps * 4;           // global row of local row 0

    // ---- phase 0: stage static_x [nrows][66] ----
    for (int e = tid; e < nrows*65; e += NT){
        int r = e / 65, j = e - r*65;
        int b = grow0 + r;
        float v;
        if (j < 64){
            int tsel = j >> 4, jj = j & 15;
            int c = cats[b*4 + tsel];
            const float* et = (tsel==0)?e0:(tsel==1)?e1:(tsel==2)?e2:e3;
            v = et[c*16 + jj];
        } else {
            v = log1pf(scale[b]);
        }
        sx_s[r*66 + j] = v;
    }
    __syncthreads();

    // ---- thread mapping: g~ = tid&63, local pair pid = tid>>6 ----
    const int gt    = tid & 63;
    const int pid   = tid >> 6;        // 0..6
    const int rbase = pid * 4;         // local rows rbase..rbase+3
    const int wInPair = (tid >> 5) & 1;
    const int lane  = tid & 31;
    const int pairLane = wInPair*32 + lane;   // 0..63 within pair
    const bool active = (pid < npair);

    // ---- pre[j][tp] = bias + static_x @ w_ih[11:76], in registers ----
    float pre[4][4];
    if (active){
        #pragma unroll
        for (int tp = 0; tp < 4; tp++){
            float bv = bias[tp*64 + gt];
            #pragma unroll
            for (int j = 0; j < 4; j++) pre[j][tp] = bv;
        }
        for (int k = 0; k < 65; k++){
            const float* wr = w_ih + (11+k)*256 + gt;
            float w0 = wr[0], w1 = wr[64], w2 = wr[128], w3 = wr[192];
            #pragma unroll
            for (int j = 0; j < 4; j++){
                float xv = sx_s[(rbase+j)*66 + k];
                pre[j][0] = fmaf(xv, w0, pre[j][0]);
                pre[j][1] = fmaf(xv, w1, pre[j][1]);
                pre[j][2] = fmaf(xv, w2, pre[j][2]);
                pre[j][3] = fmaf(xv, w3, pre[j][3]);
            }
        }
    }
    __syncthreads();   // sx readers done; wa_s can be overwritten

    // ---- pack weights: wa[kk][g~] = {i:kpair, f:kpair}, wb = {g:kpair, o:kpair} ----
    for (int idx = tid; idx < 38*64; idx += NT){
        int kk = idx >> 6, g = idx & 63;
        int k0 = 2*kk, k1 = 2*kk + 1;
        #define WK(k,c) ((k) < 64 ? w_hh[(k)*256 + (c)] : ((k) < 75 ? w_ih[((k)-64)*256 + (c)] : 0.0f))
        float4 a4, b4;
        a4.x = WK(k0, g);        a4.y = WK(k1, g);
        a4.z = WK(k0, 64 + g);   a4.w = WK(k1, 64 + g);
        b4.x = WK(k0, 128 + g);  b4.y = WK(k1, 128 + g);
        b4.z = WK(k0, 192 + g);  b4.w = WK(k1, 192 + g);
        #undef WK
        *(float4*)(wa_s + idx*4) = a4;
        *(float4*)(wb_s + idx*4) = b4;
    }
    // wout transposed: wout_s[col*64 + k] = w_out[k*2 + col]
    if (tid < 128) wout_s[(tid & 1)*64 + (tid >> 1)] = w_out[tid];
    if (tid < nrows){
        float s = scale[grow0 + tid];
        sc_s[tid]  = s;
        isc_s[tid] = 1.0f / fmaxf(s, 1e-4f);
    }
    for (int i = tid; i < 2*HBUFSZ; i += NT) hbuf[i] = 0.0f;
    __syncthreads();

    // ---- per-pair x ownership: pairLane 0..47 cover (4 rows x 12 j) ----
    int xrow = 0, xj = 0, xb = 0;
    const bool xown = active && (pairLane < 48);
    float xreg = 0.0f;
    if (xown){
        xrow = rbase + (pairLane / 12);     // local row
        xj   = pairLane % 12;
        xb   = grow0 + xrow;                // global row
        float v = 0.0f;
        if (xj >= 1 && xj <= 10) v = covar[(xb*Sq + 0)*10 + (xj-1)];
        hbuf[1*HBUFSZ + xrow*KST + 64 + xj] = v;   // x(0): prev=0, cov(0)
    }
    // head ownership: warp1-of-pair lanes 0..7 -> (4 rows x 2 outputs)
    const bool hown = active && (wInPair == 1) && (lane < 8);
    const int  hr_  = rbase + (lane >> 1);      // local row
    const int  hws  = lane & 1;
    __syncthreads();

    if (!active) return;   // idle 7th pair in 6-pair blocks (no block barriers below)

    const int barid = pid + 1;
    float creg[4] = {0.0f, 0.0f, 0.0f, 0.0f};

    for (int t = 0; t < Sq; t++){
        pbar(barid);   // pair-local: h(t-1)/x(t) of rows rbase..rbase+3 are visible
        const float* hb = hbuf + ((t+1)&1)*HBUFSZ;   // h(t-1) | x(t)

        // head for step t-1 (vectorized)
        if (hown && t > 0){
            const float4* hr4 = (const float4*)(hb + hr_*KST);
            const float4* wo4 = (const float4*)(wout_s + hws*64);
            float a0=0.f,a1=0.f,a2=0.f,a3=0.f;
            #pragma unroll
            for (int kq = 0; kq < 16; kq++){
                float4 hv = hr4[kq];
                float4 wv = wo4[kq];
                a0 = fmaf(hv.x, wv.x, a0);
                a1 = fmaf(hv.y, wv.y, a1);
                a2 = fmaf(hv.z, wv.z, a2);
                a3 = fmaf(hv.w, wv.w, a3);
            }
            float a = (a0+a1)+(a2+a3) + b_out[hws];
            float sp = (a > 15.0f) ? a : log1pf(__expf(a));
            sp += 1e-4f;
            int b = grow0 + hr_;
            if (hws == 0) out[b*Sq + (t-1)] = sp * sc_s[hr_];
            else          out[Bq*Sq + b*Sq + (t-1)] = sp;
        }
        // prefetch x(t+1)
        if (xown && t+1 < Sq){
            if (xj == 0)       xreg = target[xb*Sq + t] * isc_s[xrow];
            else if (xj <= 10) xreg = covar[(xb*Sq + t+1)*10 + (xj-1)];
            else               xreg = 0.0f;
        }

        // ================= GEMM: all 4 gate types for (4 rows x g~) =================
        ull acc[4][4];
        #pragma unroll
        for (int j = 0; j < 4; j++)
            #pragma unroll
            for (int tp = 0; tp < 4; tp++) acc[j][tp] = pack2(pre[j][tp], 0.0f);

        #pragma unroll
        for (int kk2 = 0; kk2 < 19; kk2++){
            ulonglong2 wa0 = *(const ulonglong2*)(wa_s + ((2*kk2  )*64 + gt)*4);
            ulonglong2 wb0 = *(const ulonglong2*)(wb_s + ((2*kk2  )*64 + gt)*4);
            ulonglong2 wa1 = *(const ulonglong2*)(wa_s + ((2*kk2+1)*64 + gt)*4);
            ulonglong2 wb1 = *(const ulonglong2*)(wb_s + ((2*kk2+1)*64 + gt)*4);
            #pragma unroll
            for (int j = 0; j < 4; j++){
                ulonglong2 hv = *(const ulonglong2*)(hb + (rbase+j)*KST + kk2*4);
                ffma2(acc[j][0], hv.x, wa0.x);
                ffma2(acc[j][1], hv.x, wa0.y);
                ffma2(acc[j][2], hv.x, wb0.x);
                ffma2(acc[j][3], hv.x, wb0.y);
                ffma2(acc[j][0], hv.y, wa1.x);
                ffma2(acc[j][1], hv.y, wa1.y);
                ffma2(acc[j][2], hv.y, wb1.x);
                ffma2(acc[j][3], hv.y, wb1.y);
            }
        }

        // ================= fused LSTM cell (registers) + h store =================
        {
            float* hw = hbuf + (t&1)*HBUFSZ;
            #pragma unroll
            for (int j = 0; j < 4; j++){
                float gi = fold2(acc[j][0]);
                float gf = fold2(acc[j][1]);
                float gg = fold2(acc[j][2]);
                float go = fold2(acc[j][3]);
                float i = sigf(gi);
                float f = sigf(gf);
                float g = tanh_f(gg);
                float o = sigf(go);
                float c = fmaf(f, creg[j], i*g);
                creg[j] = c;
                hw[(rbase+j)*KST + gt] = o * tanh_f(c);
            }
            if (xown) hw[xrow*KST + 64 + xj] = xreg;   // x(t+1)
        }
    }

    // final head for t = Sq-1 (pair-local sync, then read hbuf[(Sq-1)&1])
    pbar(barid);
    if (hown){
        const float4* hr4 = (const float4*)(hbuf + ((Sq-1)&1)*HBUFSZ + hr_*KST);
        const float4* wo4 = (const float4*)(wout_s + hws*64);
        float a0=0.f,a1=0.f,a2=0.f,a3=0.f;
        #pragma unroll
        for (int kq = 0; kq < 16; kq++){
            float4 hv = hr4[kq];
            float4 wv = wo4[kq];
            a0 = fmaf(hv.x, wv.x, a0);
            a1 = fmaf(hv.y, wv.y, a1);
            a2 = fmaf(hv.z, wv.z, a2);
            a3 = fmaf(hv.w, wv.w, a3);
        }
        float a = (a0+a1)+(a2+a3) + b_out[hws];
        float sp = (a > 15.0f) ? a : log1pf(__expf(a));
        sp += 1e-4f;
        int b = grow0 + hr_;
        if (hws == 0) out[b*Sq + (Sq-1)] = sp * sc_s[hr_];
        else          out[Bq*Sq + b*Sq + (Sq-1)] = sp;
    }
}

extern "C" void kernel_launch(void* const* d_in, const int* in_sizes, int n_in,
                              void* d_out, int out_size)
{
    (void)in_sizes; (void)n_in; (void)out_size;
    cudaFuncSetAttribute(deepar_kernel,
                         cudaFuncAttributeMaxDynamicSharedMemorySize, SMEM_BYTES);
    deepar_kernel<<<NBLK, NT, SMEM_BYTES>>>(
        (const float*)d_in[0],   // target
        (const float*)d_in[1],   // covariates
        (const int*)  d_in[2],   // static_cats
        (const float*)d_in[3],   // scale
        (const float*)d_in[4],   // emb0
        (const float*)d_in[5],   // emb1
        (const float*)d_in[6],   // emb2
        (const float*)d_in[7],   // emb3
        (const float*)d_in[8],   // w_ih
        (const float*)d_in[9],   // w_hh
        (const float*)d_in[10],  // bias
        (const float*)d_in[11],  // w_out
        (const float*)d_in[12],  // b_out
        (float*)d_out);
}

// round 17
// speedup vs baseline: 1.8530x; 1.0430x over previous
#include <cuda_runtime.h>
#include <math.h>

#define Bq 4096
#define Sq 512
#define NT 448
#define NBLK 148
#define NPAIRS 1024            // 4096 rows / 4 rows-per-pair
#define PMAX 7
#define KST 76                 // unified k stride: h[0:64) | x[64:75) | pad
#define HBUFSZ (PMAX*4*KST)    // 2128 floats per h|x buffer (28 rows)

typedef unsigned long long ull;

// shared layout (float offsets)
#define O_WA   0                         // wa [38 kk][64 g~] float4 = 9728
#define O_WB   (O_WA + 38*64*4)          // wb same                  = 9728
#define O_HB   (O_WB + 38*64*4)          // 2 * [28][KST]            = 4256
#define O_WOUT (O_HB + 2*HBUFSZ)         // wout TRANSPOSED [2][64]  = 128
#define O_SC   (O_WOUT + 128)            // 32
#define O_ISC  (O_SC + 32)               // 32
#define SM_TOTAL (O_ISC + 32)
#define SMEM_BYTES (SM_TOTAL*4)          // ~96 KB

// hardware tanh (sm_75+): max err ~1e-5, plenty under the 1e-3 gate
__device__ __forceinline__ float htanh(float x){
    float y; asm("tanh.approx.f32 %0, %1;" : "=f"(y) : "f"(x));
    return y;
}
__device__ __forceinline__ float sigf(float x){
    return fmaf(0.5f, htanh(0.5f*x), 0.5f);
}

__device__ __forceinline__ void ffma2(ull &d, ull a, ull b){
    asm("fma.rn.f32x2 %0, %1, %2, %0;" : "+l"(d) : "l"(a), "l"(b));
}
__device__ __forceinline__ float fold2(ull v){
    float2 f; asm("mov.b64 {%0,%1}, %2;" : "=f"(f.x), "=f"(f.y) : "l"(v));
    return f.x + f.y;
}
__device__ __forceinline__ ull pack2(float lo, float hi){
    ull v; asm("mov.b64 %0, {%1,%2};" : "=l"(v) : "f"(lo), "f"(hi));
    return v;
}
__device__ __forceinline__ void pbar(int id){
    asm volatile("bar.sync %0, 64;" :: "r"(id) : "memory");
}

__global__ void __launch_bounds__(NT,1)
deepar_kernel(const float* __restrict__ target,
              const float* __restrict__ covar,
              const int*   __restrict__ cats,
              const float* __restrict__ scale,
              const float* __restrict__ e0,
              const float* __restrict__ e1,
              const float* __restrict__ e2,
              const float* __restrict__ e3,
              const float* __restrict__ w_ih,
              const float* __restrict__ w_hh,
              const float* __restrict__ bias,
              const float* __restrict__ w_out,
              const float* __restrict__ b_out,
              float* __restrict__ out)
{
    extern __shared__ float sm[];
    float* wa_s   = sm + O_WA;
    float* wb_s   = sm + O_WB;
    float* hbuf   = sm + O_HB;
    float* wout_s = sm + O_WOUT;
    float* sc_s   = sm + O_SC;
    float* isc_s  = sm + O_ISC;
    float* sx_s   = sm + O_WA;     // alias: static_x [28][66], pre-phase only

    const int tid  = threadIdx.x;
    // balanced pair partition over blocks
    const int ps     = (int)(((long long)blockIdx.x * NPAIRS) / NBLK);
    const int pe     = (int)(((long long)(blockIdx.x+1) * NPAIRS) / NBLK);
    const int npair  = pe - ps;          // 6 or 7
    const int nrows  = npair * 4;
    const int grow0  = ps * 4;           // global row of local row 0

    // ---- phase 0: stage static_x [nrows][66] ----
    for (int e = tid; e < nrows*65; e += NT){
        int r = e / 65, j = e - r*65;
        int b = grow0 + r;
        float v;
        if (j < 64){
            int tsel = j >> 4, jj = j & 15;
            int c = cats[b*4 + tsel];
            const float* et = (tsel==0)?e0:(tsel==1)?e1:(tsel==2)?e2:e3;
            v = et[c*16 + jj];
        } else {
            v = log1pf(scale[b]);
        }
        sx_s[r*66 + j] = v;
    }
    __syncthreads();

    // ---- thread mapping: g~ = tid&63, local pair pid = tid>>6 ----
    const int gt    = tid & 63;
    const int pid   = tid >> 6;        // 0..6
    const int rbase = pid * 4;         // local rows rbase..rbase+3
    const int wInPair = (tid >> 5) & 1;
    const int lane  = tid & 31;
    const int pairLane = wInPair*32 + lane;   // 0..63 within pair
    const bool active = (pid < npair);

    // ---- pre[j][tp] = bias + static_x @ w_ih[11:76], in registers ----
    float pre[4][4];
    if (active){
        #pragma unroll
        for (int tp = 0; tp < 4; tp++){
            float bv = bias[tp*64 + gt];
            #pragma unroll
            for (int j = 0; j < 4; j++) pre[j][tp] = bv;
        }
        for (int k = 0; k < 65; k++){
            const float* wr = w_ih + (11+k)*256 + gt;
            float w0 = wr[0], w1 = wr[64], w2 = wr[128], w3 = wr[192];
            #pragma unroll
            for (int j = 0; j < 4; j++){
                float xv = sx_s[(rbase+j)*66 + k];
                pre[j][0] = fmaf(xv, w0, pre[j][0]);
                pre[j][1] = fmaf(xv, w1, pre[j][1]);
                pre[j][2] = fmaf(xv, w2, pre[j][2]);
                pre[j][3] = fmaf(xv, w3, pre[j][3]);
            }
        }
    }
    __syncthreads();   // sx readers done; wa_s can be overwritten

    // ---- pack weights: wa[kk][g~] = {i:kpair, f:kpair}, wb = {g:kpair, o:kpair} ----
    for (int idx = tid; idx < 38*64; idx += NT){
        int kk = idx >> 6, g = idx & 63;
        int k0 = 2*kk, k1 = 2*kk + 1;
        #define WK(k,c) ((k) < 64 ? w_hh[(k)*256 + (c)] : ((k) < 75 ? w_ih[((k)-64)*256 + (c)] : 0.0f))
        float4 a4, b4;
        a4.x = WK(k0, g);        a4.y = WK(k1, g);
        a4.z = WK(k0, 64 + g);   a4.w = WK(k1, 64 + g);
        b4.x = WK(k0, 128 + g);  b4.y = WK(k1, 128 + g);
        b4.z = WK(k0, 192 + g);  b4.w = WK(k1, 192 + g);
        #undef WK
        *(float4*)(wa_s + idx*4) = a4;
        *(float4*)(wb_s + idx*4) = b4;
    }
    // wout transposed: wout_s[col*64 + k] = w_out[k*2 + col]
    if (tid < 128) wout_s[(tid & 1)*64 + (tid >> 1)] = w_out[tid];
    if (tid < nrows){
        float s = scale[grow0 + tid];
        sc_s[tid]  = s;
        isc_s[tid] = 1.0f / fmaxf(s, 1e-4f);
    }
    for (int i = tid; i < 2*HBUFSZ; i += NT) hbuf[i] = 0.0f;
    __syncthreads();

    // ---- per-pair x ownership: pairLane 0..47 cover (4 rows x 12 j) ----
    int xrow = 0, xj = 0, xb = 0;
    const bool xown = active && (pairLane < 48);
    float xreg = 0.0f;
    if (xown){
        xrow = rbase + (pairLane / 12);     // local row
        xj   = pairLane % 12;
        xb   = grow0 + xrow;                // global row
        float v = 0.0f;
        if (xj >= 1 && xj <= 10) v = covar[(xb*Sq + 0)*10 + (xj-1)];
        hbuf[1*HBUFSZ + xrow*KST + 64 + xj] = v;   // x(0): prev=0, cov(0)
    }
    // head ownership: warp1-of-pair lanes 0..7 -> (4 rows x 2 outputs)
    const bool hown = active && (wInPair == 1) && (lane < 8);
    const int  hr_  = rbase + (lane >> 1);      // local row
    const int  hws  = lane & 1;
    __syncthreads();

    if (!active) return;   // idle 7th pair in 6-pair blocks (no block barriers below)

    const int barid = pid + 1;
    float creg[4] = {0.0f, 0.0f, 0.0f, 0.0f};

    for (int t = 0; t < Sq; t++){
        pbar(barid);   // pair-local: h(t-1)/x(t) of rows rbase..rbase+3 are visible
        const float* hb = hbuf + ((t+1)&1)*HBUFSZ;   // h(t-1) | x(t)

        // head for step t-1 (vectorized)
        if (hown && t > 0){
            const float4* hr4 = (const float4*)(hb + hr_*KST);
            const float4* wo4 = (const float4*)(wout_s + hws*64);
            float a0=0.f,a1=0.f,a2=0.f,a3=0.f;
            #pragma unroll
            for (int kq = 0; kq < 16; kq++){
                float4 hv = hr4[kq];
                float4 wv = wo4[kq];
                a0 = fmaf(hv.x, wv.x, a0);
                a1 = fmaf(hv.y, wv.y, a1);
                a2 = fmaf(hv.z, wv.z, a2);
                a3 = fmaf(hv.w, wv.w, a3);
            }
            float a = (a0+a1)+(a2+a3) + b_out[hws];
            float sp = (a > 15.0f) ? a : log1pf(__expf(a));
            sp += 1e-4f;
            int b = grow0 + hr_;
            if (hws == 0) out[b*Sq + (t-1)] = sp * sc_s[hr_];
            else          out[Bq*Sq + b*Sq + (t-1)] = sp;
        }
        // prefetch x(t+1)
        if (xown && t+1 < Sq){
            if (xj == 0)       xreg = target[xb*Sq + t] * isc_s[xrow];
            else if (xj <= 10) xreg = covar[(xb*Sq + t+1)*10 + (xj-1)];
            else               xreg = 0.0f;
        }

        // ================= GEMM: all 4 gate types for (4 rows x g~) =================
        ull acc[4][4];
        #pragma unroll
        for (int j = 0; j < 4; j++)
            #pragma unroll
            for (int tp = 0; tp < 4; tp++) acc[j][tp] = pack2(pre[j][tp], 0.0f);

        #pragma unroll
        for (int kk2 = 0; kk2 < 19; kk2++){
            ulonglong2 wa0 = *(const ulonglong2*)(wa_s + ((2*kk2  )*64 + gt)*4);
            ulonglong2 wb0 = *(const ulonglong2*)(wb_s + ((2*kk2  )*64 + gt)*4);
            ulonglong2 wa1 = *(const ulonglong2*)(wa_s + ((2*kk2+1)*64 + gt)*4);
            ulonglong2 wb1 = *(const ulonglong2*)(wb_s + ((2*kk2+1)*64 + gt)*4);
            #pragma unroll
            for (int j = 0; j < 4; j++){
                ulonglong2 hv = *(const ulonglong2*)(hb + (rbase+j)*KST + kk2*4);
                ffma2(acc[j][0], hv.x, wa0.x);
                ffma2(acc[j][1], hv.x, wa0.y);
                ffma2(acc[j][2], hv.x, wb0.x);
                ffma2(acc[j][3], hv.x, wb0.y);
                ffma2(acc[j][0], hv.y, wa1.x);
                ffma2(acc[j][1], hv.y, wa1.y);
                ffma2(acc[j][2], hv.y, wb1.x);
                ffma2(acc[j][3], hv.y, wb1.y);
            }
        }

        // ================= fused LSTM cell (MUFU.TANH) + h store =================
        {
            float* hw = hbuf + (t&1)*HBUFSZ;
            #pragma unroll
            for (int j = 0; j < 4; j++){
                float gi = fold2(acc[j][0]);
                float gf = fold2(acc[j][1]);
                float gg = fold2(acc[j][2]);
                float go = fold2(acc[j][3]);
                float i = sigf(gi);
                float f = sigf(gf);
                float g = htanh(gg);
                float o = sigf(go);
                float c = fmaf(f, creg[j], i*g);
                creg[j] = c;
                hw[(rbase+j)*KST + gt] = o * htanh(c);
            }
            if (xown) hw[xrow*KST + 64 + xj] = xreg;   // x(t+1)
        }
    }

    // final head for t = Sq-1 (pair-local sync, then read hbuf[(Sq-1)&1])
    pbar(barid);
    if (hown){
        const float4* hr4 = (const float4*)(hbuf + ((Sq-1)&1)*HBUFSZ + hr_*KST);
        const float4* wo4 = (const float4*)(wout_s + hws*64);
        float a0=0.f,a1=0.f,a2=0.f,a3=0.f;
        #pragma unroll
        for (int kq = 0; kq < 16; kq++){
            float4 hv = hr4[kq];
            float4 wv = wo4[kq];
            a0 = fmaf(hv.x, wv.x, a0);
            a1 = fmaf(hv.y, wv.y, a1);
            a2 = fmaf(hv.z, wv.z, a2);
            a3 = fmaf(hv.w, wv.w, a3);
        }
        float a = (a0+a1)+(a2+a3) + b_out[hws];
        float sp = (a > 15.0f) ? a : log1pf(__expf(a));
        sp += 1e-4f;
        int b = grow0 + hr_;
        if (hws == 0) out[b*Sq + (Sq-1)] = sp * sc_s[hr_];
        else          out[Bq*Sq + b*Sq + (Sq-1)] = sp;
    }
}

extern "C" void kernel_launch(void* const* d_in, const int* in_sizes, int n_in,
                              void* d_out, int out_size)
{
    (void)in_sizes; (void)n_in; (void)out_size;
    cudaFuncSetAttribute(deepar_kernel,
                         cudaFuncAttributeMaxDynamicSharedMemorySize, SMEM_BYTES);
    deepar_kernel<<<NBLK, NT, SMEM_BYTES>>>(
        (const float*)d_in[0],   // target
        (const float*)d_in[1],   // covariates
        (const int*)  d_in[2],   // static_cats
        (const float*)d_in[3],   // scale
        (const float*)d_in[4],   // emb0
        (const float*)d_in[5],   // emb1
        (const float*)d_in[6],   // emb2
        (const float*)d_in[7],   // emb3
        (const float*)d_in[8],   // w_ih
        (const float*)d_in[9],   // w_hh
        (const float*)d_in[10],  // bias
        (const float*)d_in[11],  // w_out
        (const float*)d_in[12],  // b_out
        (float*)d_out);
}